// round 1
// baseline (speedup 1.0000x reference)
#include <cuda_runtime.h>

#define NODES   4096
#define GRAPHS  128
#define GSIZE   32
#define DIN     128
#define HK      128     // HEADS*KEY_SIZE
#define DOUT    4096

// Scratch for attention output (pre-projection), [NODES, HK]
__device__ float g_attn[NODES * HK];

// ---------------------------------------------------------------------------
// Kernel A: per-graph QKV projection + exact block softmax attention.
// One CTA per graph (32 nodes). 256 threads.
// smem plan (48 KB static, at the limit):
//   phase 1/2: sm[0..4095]      = nodes tile [32][128]
//   phase 3  : sm[0..4095]      = Q  (overwrites nodes after sync)
//              sm[4096..8191]   = K
//              sm[8192..12287]  = V
// ---------------------------------------------------------------------------
__global__ __launch_bounds__(256, 1) void attn_kernel(
    const float* __restrict__ nodes,
    const float* __restrict__ Wq, const float* __restrict__ bq,
    const float* __restrict__ Wk, const float* __restrict__ bk,
    const float* __restrict__ Wv, const float* __restrict__ bv)
{
    __shared__ float sm[3 * GSIZE * HK];
    float* ns = sm;                  // nodes (aliased with qs)
    float* qs = sm;
    float* ks = sm + GSIZE * HK;
    float* vs = sm + 2 * GSIZE * HK;

    const int g   = blockIdx.x;
    const int tid = threadIdx.x;

    // ---- load node tile [32,128] ----
    {
        const float4* src = (const float4*)(nodes + (size_t)g * GSIZE * DIN);
        float4* dst = (float4*)ns;
        #pragma unroll
        for (int i = tid; i < GSIZE * DIN / 4; i += 256) dst[i] = src[i];
    }
    __syncthreads();

    // ---- QKV: [32,128] @ W[128,128] for q,k,v simultaneously ----
    // thread owns column col for 16 rows (rb selects row half)
    const int col = tid & (HK - 1);
    const int rb  = tid >> 7;   // 0 or 1
    float aq[16], ak[16], av[16];
    #pragma unroll
    for (int i = 0; i < 16; i++) { aq[i] = 0.f; ak[i] = 0.f; av[i] = 0.f; }

    for (int d4 = 0; d4 < DIN / 4; d4++) {
        const int d = d4 * 4;
        float wq[4], wk[4], wv[4];
        #pragma unroll
        for (int j = 0; j < 4; j++) {
            wq[j] = __ldg(&Wq[(d + j) * HK + col]);
            wk[j] = __ldg(&Wk[(d + j) * HK + col]);
            wv[j] = __ldg(&Wv[(d + j) * HK + col]);
        }
        #pragma unroll
        for (int i = 0; i < 16; i++) {
            const int r = rb * 16 + i;
            const float4 a = *(const float4*)&ns[r * DIN + d];
            aq[i] += a.x * wq[0]; aq[i] += a.y * wq[1];
            aq[i] += a.z * wq[2]; aq[i] += a.w * wq[3];
            ak[i] += a.x * wk[0]; ak[i] += a.y * wk[1];
            ak[i] += a.z * wk[2]; ak[i] += a.w * wk[3];
            av[i] += a.x * wv[0]; av[i] += a.y * wv[1];
            av[i] += a.z * wv[2]; av[i] += a.w * wv[3];
        }
    }
    const float bqv = __ldg(&bq[col]);
    const float bkv = __ldg(&bk[col]);
    const float bvv = __ldg(&bv[col]);
    __syncthreads();   // everyone done reading ns before qs overwrite

    #pragma unroll
    for (int i = 0; i < 16; i++) {
        const int r = rb * 16 + i;
        qs[r * HK + col] = aq[i] + bqv;
        ks[r * HK + col] = ak[i] + bkv;
        vs[r * HK + col] = av[i] + bvv;
    }
    __syncthreads();

    // ---- attention: thread (tid<128) owns one (head, query-row) pair ----
    if (tid < HK) {
        const int h = tid >> 5;
        const int i = tid & 31;
        const float* qrow = qs + i * HK + h * 32;
        float qv[32];
        #pragma unroll
        for (int k4 = 0; k4 < 8; k4++) {
            const float4 t = *(const float4*)&qrow[k4 * 4];
            qv[k4*4+0] = t.x; qv[k4*4+1] = t.y; qv[k4*4+2] = t.z; qv[k4*4+3] = t.w;
        }
        const float scale = 0.17677669529663687f;  // 1/sqrt(32)
        float lo[GSIZE];
        float mx = -1e30f;
        #pragma unroll 4
        for (int j = 0; j < GSIZE; j++) {
            const float* krow = ks + j * HK + h * 32;
            float acc = 0.f;
            #pragma unroll
            for (int k4 = 0; k4 < 8; k4++) {
                const float4 t = *(const float4*)&krow[k4 * 4];
                acc += qv[k4*4+0] * t.x; acc += qv[k4*4+1] * t.y;
                acc += qv[k4*4+2] * t.z; acc += qv[k4*4+3] * t.w;
            }
            acc *= scale;
            lo[j] = acc;
            mx = fmaxf(mx, acc);
        }
        float s = 0.f;
        #pragma unroll
        for (int j = 0; j < GSIZE; j++) { lo[j] = __expf(lo[j] - mx); s += lo[j]; }
        const float inv = 1.f / s;

        float o[32];
        #pragma unroll
        for (int k = 0; k < 32; k++) o[k] = 0.f;
        #pragma unroll 4
        for (int j = 0; j < GSIZE; j++) {
            const float a = lo[j] * inv;
            const float* vrow = vs + j * HK + h * 32;
            #pragma unroll
            for (int k4 = 0; k4 < 8; k4++) {
                const float4 t = *(const float4*)&vrow[k4 * 4];
                o[k4*4+0] += a * t.x; o[k4*4+1] += a * t.y;
                o[k4*4+2] += a * t.z; o[k4*4+3] += a * t.w;
            }
        }
        float* dstp = g_attn + ((size_t)(g * GSIZE + i)) * HK + h * 32;
        #pragma unroll
        for (int k4 = 0; k4 < 8; k4++) {
            *(float4*)&dstp[k4 * 4] =
                make_float4(o[k4*4+0], o[k4*4+1], o[k4*4+2], o[k4*4+3]);
        }
    }
}

// ---------------------------------------------------------------------------
// Kernel B: out[4096,4096] = g_attn[4096,128] @ Wo[128,4096] + bo
// CTA tile 128(M) x 64(N), full K=128 in smem, 256 threads, 8x4 microtile.
// Dynamic smem: As transposed [128][132] + Bs [128][64] = 100352 B -> 2 CTAs/SM.
// ---------------------------------------------------------------------------
#define BM   128
#define BN   64
#define APAD 4

__global__ __launch_bounds__(256, 2) void out_gemm(
    const float* __restrict__ Wo, const float* __restrict__ bo,
    float* __restrict__ out)
{
    extern __shared__ float smb[];
    float* As = smb;                       // [DIN][BM+APAD]  (As[k][m] = A[m][k])
    float* Bs = smb + DIN * (BM + APAD);   // [DIN][BN]

    const int bn0 = blockIdx.x * BN;
    const int bm0 = blockIdx.y * BM;
    const int tid = threadIdx.x;

    // load + transpose A tile
    #pragma unroll
    for (int i = tid; i < BM * DIN / 4; i += 256) {
        const int r  = i >> 5;        // 32 float4 per row
        const int c4 = i & 31;
        const float4 v = *(const float4*)&g_attn[(size_t)(bm0 + r) * DIN + c4 * 4];
        As[(c4*4+0)*(BM+APAD) + r] = v.x;
        As[(c4*4+1)*(BM+APAD) + r] = v.y;
        As[(c4*4+2)*(BM+APAD) + r] = v.z;
        As[(c4*4+3)*(BM+APAD) + r] = v.w;
    }
    // load B tile
    #pragma unroll
    for (int i = tid; i < DIN * BN / 4; i += 256) {
        const int r  = i >> 4;        // 16 float4 per row
        const int c4 = i & 15;
        *(float4*)&Bs[r * BN + c4 * 4] =
            *(const float4*)&Wo[(size_t)r * DOUT + bn0 + c4 * 4];
    }
    __syncthreads();

    const int tx = tid & 15;
    const int ty = tid >> 4;
    const int m0 = ty * 8;
    const int n0 = tx * 4;

    float c[8][4];
    #pragma unroll
    for (int i = 0; i < 8; i++)
        #pragma unroll
        for (int j = 0; j < 4; j++) c[i][j] = 0.f;

    #pragma unroll 8
    for (int k = 0; k < DIN; k++) {
        const float4 a0 = *(const float4*)&As[k * (BM + APAD) + m0];
        const float4 a1 = *(const float4*)&As[k * (BM + APAD) + m0 + 4];
        const float4 b  = *(const float4*)&Bs[k * BN + n0];
        const float am[8] = {a0.x, a0.y, a0.z, a0.w, a1.x, a1.y, a1.z, a1.w};
        const float bv[4] = {b.x, b.y, b.z, b.w};
        #pragma unroll
        for (int i = 0; i < 8; i++)
            #pragma unroll
            for (int j = 0; j < 4; j++)
                c[i][j] += am[i] * bv[j];
    }

    const float4 bias = *(const float4*)&bo[bn0 + n0];
    #pragma unroll
    for (int i = 0; i < 8; i++) {
        float4 r;
        r.x = c[i][0] + bias.x;
        r.y = c[i][1] + bias.y;
        r.z = c[i][2] + bias.z;
        r.w = c[i][3] + bias.w;
        *(float4*)&out[(size_t)(bm0 + m0 + i) * DOUT + bn0 + n0] = r;
    }
}

// ---------------------------------------------------------------------------
// Input order (metadata): nodes, n_node, Wq, bq, Wk, bk, Wv, bv, Wo, bo.
// n_node is constant 32 per graph in this problem (4096/128); the per-graph
// block structure is baked into the grid.
// ---------------------------------------------------------------------------
extern "C" void kernel_launch(void* const* d_in, const int* in_sizes, int n_in,
                              void* d_out, int out_size)
{
    const float* nodes = (const float*)d_in[0];
    const float* Wq    = (const float*)d_in[2];
    const float* bq    = (const float*)d_in[3];
    const float* Wk    = (const float*)d_in[4];
    const float* bk    = (const float*)d_in[5];
    const float* Wv    = (const float*)d_in[6];
    const float* bv    = (const float*)d_in[7];
    const float* Wo    = (const float*)d_in[8];
    const float* bo    = (const float*)d_in[9];
    float* out = (float*)d_out;

    attn_kernel<<<GRAPHS, 256>>>(nodes, Wq, bq, Wk, bk, Wv, bv);

    const size_t smem = (size_t)(DIN * (BM + APAD) + DIN * BN) * sizeof(float);
    cudaFuncSetAttribute(out_gemm, cudaFuncAttributeMaxDynamicSharedMemorySize,
                         (int)smem);
    out_gemm<<<dim3(DOUT / BN, NODES / BM), 256, smem>>>(Wo, bo, out);
}

// round 3
// speedup vs baseline: 1.9395x; 1.9395x over previous
#include <cuda_runtime.h>
#include <cuda_bf16.h>
#include <cstdint>

#define NODES   4096
#define GRAPHS  128
#define GSIZE   32
#define DIN     128
#define HK      128     // HEADS*KEY_SIZE
#define DOUT    4096

// bf16 hi/lo split operands for the output GEMM
__device__ __align__(16) __nv_bfloat16 g_Ahi[NODES * HK];
__device__ __align__(16) __nv_bfloat16 g_Alo[NODES * HK];
__device__ __align__(16) __nv_bfloat16 g_Bhi[DOUT * HK];   // WoT hi: [n][k] K-major
__device__ __align__(16) __nv_bfloat16 g_Blo[DOUT * HK];

__device__ __forceinline__ uint32_t smem_u32(const void* p) {
    uint32_t a;
    asm("{ .reg .u64 t; cvta.to.shared.u64 t, %1; cvt.u32.u64 %0, t; }"
        : "=r"(a) : "l"(p));
    return a;
}

__device__ __forceinline__ void ldsm_x4(uint32_t* d, uint32_t addr) {
    asm volatile("ldmatrix.sync.aligned.m8n8.x4.shared.b16 {%0,%1,%2,%3}, [%4];"
                 : "=r"(d[0]), "=r"(d[1]), "=r"(d[2]), "=r"(d[3]) : "r"(addr));
}
__device__ __forceinline__ void ldsm_x2(uint32_t* d, uint32_t addr) {
    asm volatile("ldmatrix.sync.aligned.m8n8.x2.shared.b16 {%0,%1}, [%2];"
                 : "=r"(d[0]), "=r"(d[1]) : "r"(addr));
}
__device__ __forceinline__ void mma16816(float* c, const uint32_t* a, const uint32_t* b) {
    asm volatile(
        "mma.sync.aligned.m16n8k16.row.col.f32.bf16.bf16.f32 "
        "{%0,%1,%2,%3}, {%4,%5,%6,%7}, {%8,%9}, {%0,%1,%2,%3};"
        : "+f"(c[0]), "+f"(c[1]), "+f"(c[2]), "+f"(c[3])
        : "r"(a[0]), "r"(a[1]), "r"(a[2]), "r"(a[3]), "r"(b[0]), "r"(b[1]));
}

__device__ __forceinline__ void split_bf16(float x, __nv_bfloat16& h, __nv_bfloat16& l) {
    h = __float2bfloat16(x);
    l = __float2bfloat16(x - __bfloat162float(h));
}

// ---------------------------------------------------------------------------
// Kernel A: per-graph QKV projection + exact block softmax attention.
// One CTA per graph (32 nodes). 256 threads. Emits bf16 hi/lo attn output.
// ---------------------------------------------------------------------------
__global__ __launch_bounds__(256, 1) void attn_kernel(
    const float* __restrict__ nodes,
    const float* __restrict__ Wq, const float* __restrict__ bq,
    const float* __restrict__ Wk, const float* __restrict__ bk,
    const float* __restrict__ Wv, const float* __restrict__ bv)
{
    __shared__ float sm[3 * GSIZE * HK];
    float* ns = sm;
    float* qs = sm;
    float* ks = sm + GSIZE * HK;
    float* vs = sm + 2 * GSIZE * HK;

    const int g   = blockIdx.x;
    const int tid = threadIdx.x;

    {
        const float4* src = (const float4*)(nodes + (size_t)g * GSIZE * DIN);
        float4* dst = (float4*)ns;
        #pragma unroll
        for (int i = tid; i < GSIZE * DIN / 4; i += 256) dst[i] = src[i];
    }
    __syncthreads();

    const int col = tid & (HK - 1);
    const int rb  = tid >> 7;
    float aq[16], ak[16], av[16];
    #pragma unroll
    for (int i = 0; i < 16; i++) { aq[i] = 0.f; ak[i] = 0.f; av[i] = 0.f; }

    for (int d4 = 0; d4 < DIN / 4; d4++) {
        const int d = d4 * 4;
        float wq[4], wk[4], wv[4];
        #pragma unroll
        for (int j = 0; j < 4; j++) {
            wq[j] = __ldg(&Wq[(d + j) * HK + col]);
            wk[j] = __ldg(&Wk[(d + j) * HK + col]);
            wv[j] = __ldg(&Wv[(d + j) * HK + col]);
        }
        #pragma unroll
        for (int i = 0; i < 16; i++) {
            const int r = rb * 16 + i;
            const float4 a = *(const float4*)&ns[r * DIN + d];
            aq[i] += a.x * wq[0]; aq[i] += a.y * wq[1];
            aq[i] += a.z * wq[2]; aq[i] += a.w * wq[3];
            ak[i] += a.x * wk[0]; ak[i] += a.y * wk[1];
            ak[i] += a.z * wk[2]; ak[i] += a.w * wk[3];
            av[i] += a.x * wv[0]; av[i] += a.y * wv[1];
            av[i] += a.z * wv[2]; av[i] += a.w * wv[3];
        }
    }
    const float bqv = __ldg(&bq[col]);
    const float bkv = __ldg(&bk[col]);
    const float bvv = __ldg(&bv[col]);
    __syncthreads();

    #pragma unroll
    for (int i = 0; i < 16; i++) {
        const int r = rb * 16 + i;
        qs[r * HK + col] = aq[i] + bqv;
        ks[r * HK + col] = ak[i] + bkv;
        vs[r * HK + col] = av[i] + bvv;
    }
    __syncthreads();

    if (tid < HK) {
        const int h = tid >> 5;
        const int i = tid & 31;
        const float* qrow = qs + i * HK + h * 32;
        float qv[32];
        #pragma unroll
        for (int k4 = 0; k4 < 8; k4++) {
            const float4 t = *(const float4*)&qrow[k4 * 4];
            qv[k4*4+0] = t.x; qv[k4*4+1] = t.y; qv[k4*4+2] = t.z; qv[k4*4+3] = t.w;
        }
        const float scale = 0.17677669529663687f;
        float lo[GSIZE];
        float mx = -1e30f;
        #pragma unroll 4
        for (int j = 0; j < GSIZE; j++) {
            const float* krow = ks + j * HK + h * 32;
            float acc = 0.f;
            #pragma unroll
            for (int k4 = 0; k4 < 8; k4++) {
                const float4 t = *(const float4*)&krow[k4 * 4];
                acc += qv[k4*4+0] * t.x; acc += qv[k4*4+1] * t.y;
                acc += qv[k4*4+2] * t.z; acc += qv[k4*4+3] * t.w;
            }
            acc *= scale;
            lo[j] = acc;
            mx = fmaxf(mx, acc);
        }
        float s = 0.f;
        #pragma unroll
        for (int j = 0; j < GSIZE; j++) { lo[j] = __expf(lo[j] - mx); s += lo[j]; }
        const float inv = 1.f / s;

        float o[32];
        #pragma unroll
        for (int k = 0; k < 32; k++) o[k] = 0.f;
        #pragma unroll 4
        for (int j = 0; j < GSIZE; j++) {
            const float a = lo[j] * inv;
            const float* vrow = vs + j * HK + h * 32;
            #pragma unroll
            for (int k4 = 0; k4 < 8; k4++) {
                const float4 t = *(const float4*)&vrow[k4 * 4];
                o[k4*4+0] += a * t.x; o[k4*4+1] += a * t.y;
                o[k4*4+2] += a * t.z; o[k4*4+3] += a * t.w;
            }
        }
        const size_t base = (size_t)(g * GSIZE + i) * HK + h * 32;
        #pragma unroll
        for (int c8 = 0; c8 < 4; c8++) {
            __align__(16) __nv_bfloat16 hb[8];
            __align__(16) __nv_bfloat16 lb[8];
            #pragma unroll
            for (int j = 0; j < 8; j++) split_bf16(o[c8 * 8 + j], hb[j], lb[j]);
            *(uint4*)&g_Ahi[base + c8 * 8] = *(uint4*)hb;
            *(uint4*)&g_Alo[base + c8 * 8] = *(uint4*)lb;
        }
    }
}

// ---------------------------------------------------------------------------
// Prep: WoT hi/lo, K-major.  WoT[n][k] = Wo[k][n].
// ---------------------------------------------------------------------------
__global__ __launch_bounds__(128) void prep_wo(const float* __restrict__ Wo)
{
    const int n = blockIdx.x * 128 + threadIdx.x;
    for (int kc = 0; kc < DIN; kc += 8) {
        __align__(16) __nv_bfloat16 hb[8];
        __align__(16) __nv_bfloat16 lb[8];
        #pragma unroll
        for (int j = 0; j < 8; j++) {
            float x = __ldg(&Wo[(size_t)(kc + j) * DOUT + n]);
            split_bf16(x, hb[j], lb[j]);
        }
        *(uint4*)&g_Bhi[(size_t)n * HK + kc] = *(uint4*)hb;
        *(uint4*)&g_Blo[(size_t)n * HK + kc] = *(uint4*)lb;
    }
}

// ---------------------------------------------------------------------------
// mma.sync GEMM: out[4096,4096] = A[4096,128] @ WoT^T + bo, bf16x3 scheme.
// CTA tile 128M x 128N, K=128 one shot. 8 warps = 2(M)x4(N), warp = 64x32.
// ---------------------------------------------------------------------------
#define BM 128
#define BN 128
#define ASTRIDE 136                 // bf16 elems per smem row (17 x 16B, odd)
#define TILE_B  (128 * ASTRIDE * 2) // 34816 bytes per tile
#define OFF_AHI 0
#define OFF_ALO (TILE_B)
#define OFF_BHI (2 * TILE_B)
#define OFF_BLO (3 * TILE_B)
#define GEMM_SMEM (4 * TILE_B)      // 139264 bytes

__global__ __launch_bounds__(256, 1) void out_gemm(
    const float* __restrict__ bo, float* __restrict__ out)
{
    extern __shared__ char smem[];
    const uint32_t sbase = smem_u32(smem);
    const int tid  = threadIdx.x;
    const int wid  = tid >> 5;
    const int lane = tid & 31;

    const int bn0 = blockIdx.x * BN;
    const int bm0 = blockIdx.y * BM;

    // ---- stage 4 tiles (each 128 rows x 128 bf16, padded rows) ----
    #pragma unroll
    for (int t = 0; t < 8; t++) {
        const int i  = tid + t * 256;           // 0..2047
        const int r  = i >> 4;
        const int k8 = i & 15;
        const uint32_t so = (uint32_t)r * (ASTRIDE * 2) + (uint32_t)k8 * 16;
        const size_t ga = (size_t)(bm0 + r) * HK + k8 * 8;
        const size_t gb = (size_t)(bn0 + r) * HK + k8 * 8;
        *(uint4*)(smem + OFF_AHI + so) = *(const uint4*)&g_Ahi[ga];
        *(uint4*)(smem + OFF_ALO + so) = *(const uint4*)&g_Alo[ga];
        *(uint4*)(smem + OFF_BHI + so) = *(const uint4*)&g_Bhi[gb];
        *(uint4*)(smem + OFF_BLO + so) = *(const uint4*)&g_Blo[gb];
    }
    __syncthreads();

    const int wm0 = (wid >> 2) * 64;   // warp M offset within CTA tile
    const int wn0 = (wid & 3) * 32;    // warp N offset

    float acc[4][4][4];
    #pragma unroll
    for (int mf = 0; mf < 4; mf++)
        #pragma unroll
        for (int nf = 0; nf < 4; nf++)
            #pragma unroll
            for (int r = 0; r < 4; r++) acc[mf][nf][r] = 0.f;

    // ldmatrix per-thread row/col selectors
    const int a_row = lane & 15;                 // + mf*16 + wm0
    const int a_col = (lane >> 4) * 8;           // + k0
    const int b_row = lane & 7;                  // + nf*8 + wn0
    const int b_col = ((lane >> 3) & 1) * 8;     // + k0 (threads 0-15 used)

    #pragma unroll
    for (int ks = 0; ks < 8; ks++) {
        const int k0 = ks * 16;
        uint32_t aHi[4][4], aLo[4][4], bHi[4][2], bLo[4][2];
        #pragma unroll
        for (int mf = 0; mf < 4; mf++) {
            const uint32_t off =
                (uint32_t)(wm0 + mf * 16 + a_row) * (ASTRIDE * 2)
                + (uint32_t)(k0 + a_col) * 2;
            ldsm_x4(aHi[mf], sbase + OFF_AHI + off);
            ldsm_x4(aLo[mf], sbase + OFF_ALO + off);
        }
        #pragma unroll
        for (int nf = 0; nf < 4; nf++) {
            const uint32_t off =
                (uint32_t)(wn0 + nf * 8 + b_row) * (ASTRIDE * 2)
                + (uint32_t)(k0 + b_col) * 2;
            ldsm_x2(bHi[nf], sbase + OFF_BHI + off);
            ldsm_x2(bLo[nf], sbase + OFF_BLO + off);
        }
        #pragma unroll
        for (int mf = 0; mf < 4; mf++)
            #pragma unroll
            for (int nf = 0; nf < 4; nf++) {
                mma16816(acc[mf][nf], aHi[mf], bHi[nf]);
                mma16816(acc[mf][nf], aHi[mf], bLo[nf]);
                mma16816(acc[mf][nf], aLo[mf], bHi[nf]);
            }
    }

    // ---- epilogue: bias + store (float2 per fragment half) ----
    const int er = lane >> 2;          // 0..7
    const int ec = (lane & 3) * 2;     // 0,2,4,6
    #pragma unroll
    for (int nf = 0; nf < 4; nf++) {
        const int n = bn0 + wn0 + nf * 8 + ec;
        const float2 bv = *(const float2*)&bo[n];
        #pragma unroll
        for (int mf = 0; mf < 4; mf++) {
            const int m = bm0 + wm0 + mf * 16 + er;
            float2 v0, v1;
            v0.x = acc[mf][nf][0] + bv.x;
            v0.y = acc[mf][nf][1] + bv.y;
            v1.x = acc[mf][nf][2] + bv.x;
            v1.y = acc[mf][nf][3] + bv.y;
            *(float2*)&out[(size_t)m * DOUT + n]       = v0;
            *(float2*)&out[(size_t)(m + 8) * DOUT + n] = v1;
        }
    }
}

// ---------------------------------------------------------------------------
// Inputs: nodes, n_node, Wq, bq, Wk, bk, Wv, bv, Wo, bo.
// ---------------------------------------------------------------------------
extern "C" void kernel_launch(void* const* d_in, const int* in_sizes, int n_in,
                              void* d_out, int out_size)
{
    const float* nodes = (const float*)d_in[0];
    const float* Wq    = (const float*)d_in[2];
    const float* bq    = (const float*)d_in[3];
    const float* Wk    = (const float*)d_in[4];
    const float* bk    = (const float*)d_in[5];
    const float* Wv    = (const float*)d_in[6];
    const float* bv    = (const float*)d_in[7];
    const float* Wo    = (const float*)d_in[8];
    const float* bo    = (const float*)d_in[9];
    float* out = (float*)d_out;

    prep_wo<<<DOUT / 128, 128>>>(Wo);
    attn_kernel<<<GRAPHS, 256>>>(nodes, Wq, bq, Wk, bk, Wv, bv);

    cudaFuncSetAttribute(out_gemm, cudaFuncAttributeMaxDynamicSharedMemorySize,
                         GEMM_SMEM);
    out_gemm<<<dim3(DOUT / BN, NODES / BM), 256, GEMM_SMEM>>>(bo, out);
}

// round 4
// speedup vs baseline: 2.1923x; 1.1303x over previous
#include <cuda_runtime.h>
#include <cuda_bf16.h>
#include <cstdint>

#define NODES   4096
#define GRAPHS  128
#define GSIZE   32
#define DIN     128
#define HK      128     // HEADS*KEY_SIZE
#define DOUT    4096

// bf16 hi/lo split operands for the output GEMM
__device__ __align__(16) __nv_bfloat16 g_Ahi[NODES * HK];
__device__ __align__(16) __nv_bfloat16 g_Alo[NODES * HK];
__device__ __align__(16) __nv_bfloat16 g_Bhi[DOUT * HK];   // WoT hi: [n][k] K-major
__device__ __align__(16) __nv_bfloat16 g_Blo[DOUT * HK];

__device__ __forceinline__ uint32_t smem_u32(const void* p) {
    uint32_t a;
    asm("{ .reg .u64 t; cvta.to.shared.u64 t, %1; cvt.u32.u64 %0, t; }"
        : "=r"(a) : "l"(p));
    return a;
}

__device__ __forceinline__ void ldsm_x4(uint32_t* d, uint32_t addr) {
    asm volatile("ldmatrix.sync.aligned.m8n8.x4.shared.b16 {%0,%1,%2,%3}, [%4];"
                 : "=r"(d[0]), "=r"(d[1]), "=r"(d[2]), "=r"(d[3]) : "r"(addr));
}
__device__ __forceinline__ void ldsm_x2(uint32_t* d, uint32_t addr) {
    asm volatile("ldmatrix.sync.aligned.m8n8.x2.shared.b16 {%0,%1}, [%2];"
                 : "=r"(d[0]), "=r"(d[1]) : "r"(addr));
}
__device__ __forceinline__ void mma16816(float* c, const uint32_t* a, const uint32_t* b) {
    asm volatile(
        "mma.sync.aligned.m16n8k16.row.col.f32.bf16.bf16.f32 "
        "{%0,%1,%2,%3}, {%4,%5,%6,%7}, {%8,%9}, {%0,%1,%2,%3};"
        : "+f"(c[0]), "+f"(c[1]), "+f"(c[2]), "+f"(c[3])
        : "r"(a[0]), "r"(a[1]), "r"(a[2]), "r"(a[3]), "r"(b[0]), "r"(b[1]));
}

__device__ __forceinline__ void split_bf16(float x, __nv_bfloat16& h, __nv_bfloat16& l) {
    h = __float2bfloat16(x);
    l = __float2bfloat16(x - __bfloat162float(h));
}

// ---------------------------------------------------------------------------
// Kernel A: per-graph QKV projection + exact block softmax attention.
// One CTA per graph (32 nodes). 256 threads. Emits bf16 hi/lo attn output.
// ---------------------------------------------------------------------------
__global__ __launch_bounds__(256, 1) void attn_kernel(
    const float* __restrict__ nodes,
    const float* __restrict__ Wq, const float* __restrict__ bq,
    const float* __restrict__ Wk, const float* __restrict__ bk,
    const float* __restrict__ Wv, const float* __restrict__ bv)
{
    __shared__ float sm[3 * GSIZE * HK];
    float* ns = sm;
    float* qs = sm;
    float* ks = sm + GSIZE * HK;
    float* vs = sm + 2 * GSIZE * HK;

    const int g   = blockIdx.x;
    const int tid = threadIdx.x;

    {
        const float4* src = (const float4*)(nodes + (size_t)g * GSIZE * DIN);
        float4* dst = (float4*)ns;
        #pragma unroll
        for (int i = tid; i < GSIZE * DIN / 4; i += 256) dst[i] = src[i];
    }
    __syncthreads();

    const int col = tid & (HK - 1);
    const int rb  = tid >> 7;
    float aq[16], ak[16], av[16];
    #pragma unroll
    for (int i = 0; i < 16; i++) { aq[i] = 0.f; ak[i] = 0.f; av[i] = 0.f; }

    for (int d4 = 0; d4 < DIN / 4; d4++) {
        const int d = d4 * 4;
        float wq[4], wk[4], wv[4];
        #pragma unroll
        for (int j = 0; j < 4; j++) {
            wq[j] = __ldg(&Wq[(d + j) * HK + col]);
            wk[j] = __ldg(&Wk[(d + j) * HK + col]);
            wv[j] = __ldg(&Wv[(d + j) * HK + col]);
        }
        #pragma unroll
        for (int i = 0; i < 16; i++) {
            const int r = rb * 16 + i;
            const float4 a = *(const float4*)&ns[r * DIN + d];
            aq[i] += a.x * wq[0]; aq[i] += a.y * wq[1];
            aq[i] += a.z * wq[2]; aq[i] += a.w * wq[3];
            ak[i] += a.x * wk[0]; ak[i] += a.y * wk[1];
            ak[i] += a.z * wk[2]; ak[i] += a.w * wk[3];
            av[i] += a.x * wv[0]; av[i] += a.y * wv[1];
            av[i] += a.z * wv[2]; av[i] += a.w * wv[3];
        }
    }
    const float bqv = __ldg(&bq[col]);
    const float bkv = __ldg(&bk[col]);
    const float bvv = __ldg(&bv[col]);
    __syncthreads();

    #pragma unroll
    for (int i = 0; i < 16; i++) {
        const int r = rb * 16 + i;
        qs[r * HK + col] = aq[i] + bqv;
        ks[r * HK + col] = ak[i] + bkv;
        vs[r * HK + col] = av[i] + bvv;
    }
    __syncthreads();

    if (tid < HK) {
        const int h = tid >> 5;
        const int i = tid & 31;
        const float* qrow = qs + i * HK + h * 32;
        float qv[32];
        #pragma unroll
        for (int k4 = 0; k4 < 8; k4++) {
            const float4 t = *(const float4*)&qrow[k4 * 4];
            qv[k4*4+0] = t.x; qv[k4*4+1] = t.y; qv[k4*4+2] = t.z; qv[k4*4+3] = t.w;
        }
        const float scale = 0.17677669529663687f;
        float lo[GSIZE];
        float mx = -1e30f;
        #pragma unroll 4
        for (int j = 0; j < GSIZE; j++) {
            const float* krow = ks + j * HK + h * 32;
            float acc = 0.f;
            #pragma unroll
            for (int k4 = 0; k4 < 8; k4++) {
                const float4 t = *(const float4*)&krow[k4 * 4];
                acc += qv[k4*4+0] * t.x; acc += qv[k4*4+1] * t.y;
                acc += qv[k4*4+2] * t.z; acc += qv[k4*4+3] * t.w;
            }
            acc *= scale;
            lo[j] = acc;
            mx = fmaxf(mx, acc);
        }
        float s = 0.f;
        #pragma unroll
        for (int j = 0; j < GSIZE; j++) { lo[j] = __expf(lo[j] - mx); s += lo[j]; }
        const float inv = 1.f / s;

        float o[32];
        #pragma unroll
        for (int k = 0; k < 32; k++) o[k] = 0.f;
        #pragma unroll 4
        for (int j = 0; j < GSIZE; j++) {
            const float a = lo[j] * inv;
            const float* vrow = vs + j * HK + h * 32;
            #pragma unroll
            for (int k4 = 0; k4 < 8; k4++) {
                const float4 t = *(const float4*)&vrow[k4 * 4];
                o[k4*4+0] += a * t.x; o[k4*4+1] += a * t.y;
                o[k4*4+2] += a * t.z; o[k4*4+3] += a * t.w;
            }
        }
        const size_t base = (size_t)(g * GSIZE + i) * HK + h * 32;
        #pragma unroll
        for (int c8 = 0; c8 < 4; c8++) {
            __align__(16) __nv_bfloat16 hb[8];
            __align__(16) __nv_bfloat16 lb[8];
            #pragma unroll
            for (int j = 0; j < 8; j++) split_bf16(o[c8 * 8 + j], hb[j], lb[j]);
            *(uint4*)&g_Ahi[base + c8 * 8] = *(uint4*)hb;
            *(uint4*)&g_Alo[base + c8 * 8] = *(uint4*)lb;
        }
    }
}

// ---------------------------------------------------------------------------
// Prep: WoT hi/lo, K-major.  WoT[n][k] = Wo[k][n].
// Grid 16x16 CTAs x 256 thr: thread = (n, 8-k chunk). Coalesced reads.
// ---------------------------------------------------------------------------
__global__ __launch_bounds__(256) void prep_wo(const float* __restrict__ Wo)
{
    const int n  = blockIdx.x * 256 + threadIdx.x;
    const int kc = blockIdx.y * 8;
    __align__(16) __nv_bfloat16 hb[8];
    __align__(16) __nv_bfloat16 lb[8];
    #pragma unroll
    for (int j = 0; j < 8; j++) {
        float x = __ldg(&Wo[(size_t)(kc + j) * DOUT + n]);
        split_bf16(x, hb[j], lb[j]);
    }
    *(uint4*)&g_Bhi[(size_t)n * HK + kc] = *(uint4*)hb;
    *(uint4*)&g_Blo[(size_t)n * HK + kc] = *(uint4*)lb;
}

// ---------------------------------------------------------------------------
// mma.sync GEMM: out[4096,4096] = A[4096,128] @ WoT^T + bo, bf16x3 scheme.
// CTA tile 128M x 64N, K=128 one shot. 8 warps = 4(M)x2(N), warp = 32x32.
// smem 102KB -> 2 CTAs/SM: staging of one CTA hides under MMA of the other.
// ---------------------------------------------------------------------------
#define BM 128
#define BN 64
#define ASTRIDE 136                     // bf16 elems per smem row (17 x 16B, odd)
#define TILE_A  (BM * ASTRIDE * 2)      // 34816 B
#define TILE_Bb (BN * ASTRIDE * 2)      // 17408 B
#define OFF_AHI 0
#define OFF_ALO (TILE_A)
#define OFF_BHI (2 * TILE_A)
#define OFF_BLO (2 * TILE_A + TILE_Bb)
#define GEMM_SMEM (2 * TILE_A + 2 * TILE_Bb)   // 104448 B

__global__ __launch_bounds__(256, 2) void out_gemm(
    const float* __restrict__ bo, float* __restrict__ out)
{
    extern __shared__ char smem[];
    const uint32_t sbase = smem_u32(smem);
    const int tid  = threadIdx.x;
    const int wid  = tid >> 5;
    const int lane = tid & 31;

    const int bn0 = blockIdx.x * BN;
    const int bm0 = blockIdx.y * BM;

    // ---- stage A tiles (128 rows) ----
    #pragma unroll
    for (int t = 0; t < (BM * 16) / 256; t++) {
        const int i  = tid + t * 256;
        const int r  = i >> 4;
        const int k8 = i & 15;
        const uint32_t so = (uint32_t)r * (ASTRIDE * 2) + (uint32_t)k8 * 16;
        const size_t ga = (size_t)(bm0 + r) * HK + k8 * 8;
        *(uint4*)(smem + OFF_AHI + so) = *(const uint4*)&g_Ahi[ga];
        *(uint4*)(smem + OFF_ALO + so) = *(const uint4*)&g_Alo[ga];
    }
    // ---- stage B tiles (64 rows) ----
    #pragma unroll
    for (int t = 0; t < (BN * 16) / 256; t++) {
        const int i  = tid + t * 256;
        const int r  = i >> 4;
        const int k8 = i & 15;
        const uint32_t so = (uint32_t)r * (ASTRIDE * 2) + (uint32_t)k8 * 16;
        const size_t gb = (size_t)(bn0 + r) * HK + k8 * 8;
        *(uint4*)(smem + OFF_BHI + so) = *(const uint4*)&g_Bhi[gb];
        *(uint4*)(smem + OFF_BLO + so) = *(const uint4*)&g_Blo[gb];
    }
    __syncthreads();

    const int wm0 = (wid & 3) * 32;    // warp M offset (4 warps over 128)
    const int wn0 = (wid >> 2) * 32;   // warp N offset (2 warps over 64)

    float acc[2][4][4];
    #pragma unroll
    for (int mf = 0; mf < 2; mf++)
        #pragma unroll
        for (int nf = 0; nf < 4; nf++)
            #pragma unroll
            for (int r = 0; r < 4; r++) acc[mf][nf][r] = 0.f;

    const int a_row = lane & 15;
    const int a_col = (lane >> 4) * 8;
    const int b_row = lane & 7;
    const int b_col = ((lane >> 3) & 1) * 8;

    #pragma unroll
    for (int ks = 0; ks < 8; ks++) {
        const int k0 = ks * 16;
        uint32_t aHi[2][4], aLo[2][4], bHi[4][2], bLo[4][2];
        #pragma unroll
        for (int mf = 0; mf < 2; mf++) {
            const uint32_t off =
                (uint32_t)(wm0 + mf * 16 + a_row) * (ASTRIDE * 2)
                + (uint32_t)(k0 + a_col) * 2;
            ldsm_x4(aHi[mf], sbase + OFF_AHI + off);
            ldsm_x4(aLo[mf], sbase + OFF_ALO + off);
        }
        #pragma unroll
        for (int nf = 0; nf < 4; nf++) {
            const uint32_t off =
                (uint32_t)(wn0 + nf * 8 + b_row) * (ASTRIDE * 2)
                + (uint32_t)(k0 + b_col) * 2;
            ldsm_x2(bHi[nf], sbase + OFF_BHI + off);
            ldsm_x2(bLo[nf], sbase + OFF_BLO + off);
        }
        #pragma unroll
        for (int mf = 0; mf < 2; mf++)
            #pragma unroll
            for (int nf = 0; nf < 4; nf++) {
                mma16816(acc[mf][nf], aHi[mf], bHi[nf]);
                mma16816(acc[mf][nf], aHi[mf], bLo[nf]);
                mma16816(acc[mf][nf], aLo[mf], bHi[nf]);
            }
    }

    // ---- epilogue: bias + store (float2 per fragment half) ----
    const int er = lane >> 2;
    const int ec = (lane & 3) * 2;
    #pragma unroll
    for (int nf = 0; nf < 4; nf++) {
        const int n = bn0 + wn0 + nf * 8 + ec;
        const float2 bv = *(const float2*)&bo[n];
        #pragma unroll
        for (int mf = 0; mf < 2; mf++) {
            const int m = bm0 + wm0 + mf * 16 + er;
            float2 v0, v1;
            v0.x = acc[mf][nf][0] + bv.x;
            v0.y = acc[mf][nf][1] + bv.y;
            v1.x = acc[mf][nf][2] + bv.x;
            v1.y = acc[mf][nf][3] + bv.y;
            *(float2*)&out[(size_t)m * DOUT + n]       = v0;
            *(float2*)&out[(size_t)(m + 8) * DOUT + n] = v1;
        }
    }
}

// ---------------------------------------------------------------------------
// Inputs: nodes, n_node, Wq, bq, Wk, bk, Wv, bv, Wo, bo.
// ---------------------------------------------------------------------------
extern "C" void kernel_launch(void* const* d_in, const int* in_sizes, int n_in,
                              void* d_out, int out_size)
{
    const float* nodes = (const float*)d_in[0];
    const float* Wq    = (const float*)d_in[2];
    const float* bq    = (const float*)d_in[3];
    const float* Wk    = (const float*)d_in[4];
    const float* bk    = (const float*)d_in[5];
    const float* Wv    = (const float*)d_in[6];
    const float* bv    = (const float*)d_in[7];
    const float* Wo    = (const float*)d_in[8];
    const float* bo    = (const float*)d_in[9];
    float* out = (float*)d_out;

    prep_wo<<<dim3(DOUT / 256, DIN / 8), 256>>>(Wo);
    attn_kernel<<<GRAPHS, 256>>>(nodes, Wq, bq, Wk, bk, Wv, bv);

    cudaFuncSetAttribute(out_gemm, cudaFuncAttributeMaxDynamicSharedMemorySize,
                         GEMM_SMEM);
    out_gemm<<<dim3(DOUT / BN, NODES / BM), 256, GEMM_SMEM>>>(bo, out);
}

// round 5
// speedup vs baseline: 2.6139x; 1.1923x over previous
#include <cuda_runtime.h>
#include <cuda_bf16.h>
#include <cstdint>

#define NODES   4096
#define GRAPHS  128
#define GSIZE   32
#define DIN     128
#define HK      128     // HEADS*KEY_SIZE
#define QKVN    384     // 3*HK
#define DOUT    4096

// bf16 hi/lo split operands
__device__ __align__(16) __nv_bfloat16 g_Xhi[NODES * DIN];
__device__ __align__(16) __nv_bfloat16 g_Xlo[NODES * DIN];
__device__ __align__(16) __nv_bfloat16 g_Whi[QKVN * DIN];    // [Wq|Wk|Wv]^T K-major
__device__ __align__(16) __nv_bfloat16 g_Wlo[QKVN * DIN];
__device__ __align__(16) float         g_bqkv[QKVN];
__device__ __align__(16) float         g_qkv[NODES * QKVN];  // q|k|v per node
__device__ __align__(16) __nv_bfloat16 g_Ahi[NODES * HK];
__device__ __align__(16) __nv_bfloat16 g_Alo[NODES * HK];
__device__ __align__(16) __nv_bfloat16 g_Bhi[DOUT * HK];     // WoT K-major
__device__ __align__(16) __nv_bfloat16 g_Blo[DOUT * HK];

__device__ __forceinline__ uint32_t smem_u32(const void* p) {
    uint32_t a;
    asm("{ .reg .u64 t; cvta.to.shared.u64 t, %1; cvt.u32.u64 %0, t; }"
        : "=r"(a) : "l"(p));
    return a;
}
__device__ __forceinline__ void ldsm_x4(uint32_t* d, uint32_t addr) {
    asm volatile("ldmatrix.sync.aligned.m8n8.x4.shared.b16 {%0,%1,%2,%3}, [%4];"
                 : "=r"(d[0]), "=r"(d[1]), "=r"(d[2]), "=r"(d[3]) : "r"(addr));
}
__device__ __forceinline__ void ldsm_x2(uint32_t* d, uint32_t addr) {
    asm volatile("ldmatrix.sync.aligned.m8n8.x2.shared.b16 {%0,%1}, [%2];"
                 : "=r"(d[0]), "=r"(d[1]) : "r"(addr));
}
__device__ __forceinline__ void mma16816(float* c, const uint32_t* a, const uint32_t* b) {
    asm volatile(
        "mma.sync.aligned.m16n8k16.row.col.f32.bf16.bf16.f32 "
        "{%0,%1,%2,%3}, {%4,%5,%6,%7}, {%8,%9}, {%0,%1,%2,%3};"
        : "+f"(c[0]), "+f"(c[1]), "+f"(c[2]), "+f"(c[3])
        : "r"(a[0]), "r"(a[1]), "r"(a[2]), "r"(a[3]), "r"(b[0]), "r"(b[1]));
}
__device__ __forceinline__ void split_bf16(float x, __nv_bfloat16& h, __nv_bfloat16& l) {
    h = __float2bfloat16(x);
    l = __float2bfloat16(x - __bfloat162float(h));
}

// ---------------------------------------------------------------------------
// prep_all: all fp32 -> bf16 hi/lo conversions in one launch.
//   blocks [0,256)   : Wo -> g_Bhi/g_Blo (transpose to K-major)
//   blocks [256,512) : nodes -> g_Xhi/g_Xlo (row-major copy-convert)
//   blocks [512,536) : Wq|Wk|Wv -> g_Whi/g_Wlo (transpose) + bias concat
// ---------------------------------------------------------------------------
__global__ __launch_bounds__(256) void prep_all(
    const float* __restrict__ nodes,
    const float* __restrict__ Wq, const float* __restrict__ bq,
    const float* __restrict__ Wk, const float* __restrict__ bk,
    const float* __restrict__ Wv, const float* __restrict__ bv,
    const float* __restrict__ Wo)
{
    const int p   = blockIdx.x;
    const int tid = threadIdx.x;
    __align__(16) __nv_bfloat16 hb[8];
    __align__(16) __nv_bfloat16 lb[8];

    if (p < 256) {                      // Wo transpose: n coalesced over tid
        const int n  = (p & 15) * 256 + tid;
        const int kc = (p >> 4) * 8;
        #pragma unroll
        for (int j = 0; j < 8; j++) {
            float x = __ldg(&Wo[(size_t)(kc + j) * DOUT + n]);
            split_bf16(x, hb[j], lb[j]);
        }
        *(uint4*)&g_Bhi[(size_t)n * HK + kc] = *(uint4*)hb;
        *(uint4*)&g_Blo[(size_t)n * HK + kc] = *(uint4*)lb;
    } else if (p < 512) {               // nodes copy-convert (row-major both)
        const int q  = p - 256;
        const int r  = q * 16 + (tid >> 4);
        const int kc = (tid & 15) * 8;
        const float4 v0 = *(const float4*)&nodes[(size_t)r * DIN + kc];
        const float4 v1 = *(const float4*)&nodes[(size_t)r * DIN + kc + 4];
        const float xs[8] = {v0.x, v0.y, v0.z, v0.w, v1.x, v1.y, v1.z, v1.w};
        #pragma unroll
        for (int j = 0; j < 8; j++) split_bf16(xs[j], hb[j], lb[j]);
        *(uint4*)&g_Xhi[(size_t)r * DIN + kc] = *(uint4*)hb;
        *(uint4*)&g_Xlo[(size_t)r * DIN + kc] = *(uint4*)lb;
    } else {                            // Wq|Wk|Wv transpose + bias
        const int idx = (p - 512) * 256 + tid;   // [0, 6144)
        const int n   = idx >> 4;                // [0, 384)
        const int kc  = (idx & 15) * 8;
        const float* W = (n < HK) ? Wq : (n < 2 * HK) ? Wk : Wv;
        const float* b = (n < HK) ? bq : (n < 2 * HK) ? bk : bv;
        const int nl = n & (HK - 1);
        #pragma unroll
        for (int j = 0; j < 8; j++) {
            float x = __ldg(&W[(size_t)(kc + j) * HK + nl]);
            split_bf16(x, hb[j], lb[j]);
        }
        *(uint4*)&g_Whi[(size_t)n * DIN + kc] = *(uint4*)hb;
        *(uint4*)&g_Wlo[(size_t)n * DIN + kc] = *(uint4*)lb;
        if ((idx & 15) == 0) g_bqkv[n] = __ldg(&b[nl]);
    }
}

// ---------------------------------------------------------------------------
// Shared GEMM body (bf16x3): C[BMxBN] = A[BMx128] @ B[BNx128]^T + bias
// 8 warps = 4(M)x2(N), warp tile 32x32.
// ---------------------------------------------------------------------------
#define BM 128
#define BN 64
#define ASTRIDE 136                     // bf16 elems per smem row (odd 16B units)
#define TILE_A  (BM * ASTRIDE * 2)      // 34816 B
#define TILE_Bb (BN * ASTRIDE * 2)      // 17408 B
#define OFF_AHI 0
#define OFF_ALO (TILE_A)
#define OFF_BHI (2 * TILE_A)
#define OFF_BLO (2 * TILE_A + TILE_Bb)
#define GEMM_SMEM (2 * TILE_A + 2 * TILE_Bb)   // 104448 B

template <int OUTW>
__device__ __forceinline__ void gemm_body(
    const __nv_bfloat16* __restrict__ Ahi, const __nv_bfloat16* __restrict__ Alo,
    const __nv_bfloat16* __restrict__ Bhi, const __nv_bfloat16* __restrict__ Blo,
    const float* __restrict__ bias, float* __restrict__ outp,
    int bm0, int bn0)
{
    extern __shared__ char smem[];
    const uint32_t sbase = smem_u32(smem);
    const int tid  = threadIdx.x;
    const int wid  = tid >> 5;
    const int lane = tid & 31;

    #pragma unroll
    for (int t = 0; t < (BM * 16) / 256; t++) {
        const int i  = tid + t * 256;
        const int r  = i >> 4;
        const int k8 = i & 15;
        const uint32_t so = (uint32_t)r * (ASTRIDE * 2) + (uint32_t)k8 * 16;
        const size_t ga = (size_t)(bm0 + r) * DIN + k8 * 8;
        *(uint4*)(smem + OFF_AHI + so) = *(const uint4*)&Ahi[ga];
        *(uint4*)(smem + OFF_ALO + so) = *(const uint4*)&Alo[ga];
    }
    #pragma unroll
    for (int t = 0; t < (BN * 16) / 256; t++) {
        const int i  = tid + t * 256;
        const int r  = i >> 4;
        const int k8 = i & 15;
        const uint32_t so = (uint32_t)r * (ASTRIDE * 2) + (uint32_t)k8 * 16;
        const size_t gb = (size_t)(bn0 + r) * DIN + k8 * 8;
        *(uint4*)(smem + OFF_BHI + so) = *(const uint4*)&Bhi[gb];
        *(uint4*)(smem + OFF_BLO + so) = *(const uint4*)&Blo[gb];
    }
    __syncthreads();

    const int wm0 = (wid & 3) * 32;
    const int wn0 = (wid >> 2) * 32;

    float acc[2][4][4];
    #pragma unroll
    for (int mf = 0; mf < 2; mf++)
        #pragma unroll
        for (int nf = 0; nf < 4; nf++)
            #pragma unroll
            for (int r = 0; r < 4; r++) acc[mf][nf][r] = 0.f;

    const int a_row = lane & 15;
    const int a_col = (lane >> 4) * 8;
    const int b_row = lane & 7;
    const int b_col = ((lane >> 3) & 1) * 8;

    #pragma unroll
    for (int ks = 0; ks < 8; ks++) {
        const int k0 = ks * 16;
        uint32_t aHi[2][4], aLo[2][4], bHi[4][2], bLo[4][2];
        #pragma unroll
        for (int mf = 0; mf < 2; mf++) {
            const uint32_t off =
                (uint32_t)(wm0 + mf * 16 + a_row) * (ASTRIDE * 2)
                + (uint32_t)(k0 + a_col) * 2;
            ldsm_x4(aHi[mf], sbase + OFF_AHI + off);
            ldsm_x4(aLo[mf], sbase + OFF_ALO + off);
        }
        #pragma unroll
        for (int nf = 0; nf < 4; nf++) {
            const uint32_t off =
                (uint32_t)(wn0 + nf * 8 + b_row) * (ASTRIDE * 2)
                + (uint32_t)(k0 + b_col) * 2;
            ldsm_x2(bHi[nf], sbase + OFF_BHI + off);
            ldsm_x2(bLo[nf], sbase + OFF_BLO + off);
        }
        #pragma unroll
        for (int mf = 0; mf < 2; mf++)
            #pragma unroll
            for (int nf = 0; nf < 4; nf++) {
                mma16816(acc[mf][nf], aHi[mf], bHi[nf]);
                mma16816(acc[mf][nf], aHi[mf], bLo[nf]);
                mma16816(acc[mf][nf], aLo[mf], bHi[nf]);
            }
    }

    const int er = lane >> 2;
    const int ec = (lane & 3) * 2;
    #pragma unroll
    for (int nf = 0; nf < 4; nf++) {
        const int n = bn0 + wn0 + nf * 8 + ec;
        const float2 bv = *(const float2*)&bias[n];
        #pragma unroll
        for (int mf = 0; mf < 2; mf++) {
            const int m = bm0 + wm0 + mf * 16 + er;
            float2 v0, v1;
            v0.x = acc[mf][nf][0] + bv.x;
            v0.y = acc[mf][nf][1] + bv.y;
            v1.x = acc[mf][nf][2] + bv.x;
            v1.y = acc[mf][nf][3] + bv.y;
            *(float2*)&outp[(size_t)m * OUTW + n]       = v0;
            *(float2*)&outp[(size_t)(m + 8) * OUTW + n] = v1;
        }
    }
}

__global__ __launch_bounds__(256, 2) void qkv_gemm()
{
    gemm_body<QKVN>(g_Xhi, g_Xlo, g_Whi, g_Wlo, g_bqkv, g_qkv,
                    blockIdx.y * BM, blockIdx.x * BN);
}

__global__ __launch_bounds__(256, 2) void out_gemm(
    const float* __restrict__ bo, float* __restrict__ out)
{
    gemm_body<DOUT>(g_Ahi, g_Alo, g_Bhi, g_Blo, bo, out,
                    blockIdx.y * BM, blockIdx.x * BN);
}

// ---------------------------------------------------------------------------
// attn2: per-graph softmax attention on precomputed q/k/v.
// One CTA per graph. 256 threads load 32x384 fp32 block; 128 threads compute.
// ---------------------------------------------------------------------------
__global__ __launch_bounds__(256, 1) void attn2()
{
    __shared__ float sm[GSIZE * QKVN];   // 49152 B
    const int g   = blockIdx.x;
    const int tid = threadIdx.x;

    {
        const float4* src = (const float4*)(g_qkv + (size_t)g * GSIZE * QKVN);
        float4* dst = (float4*)sm;
        #pragma unroll
        for (int i = tid; i < GSIZE * QKVN / 4; i += 256) dst[i] = src[i];
    }
    __syncthreads();

    if (tid < HK) {
        const int h = tid >> 5;
        const int i = tid & 31;
        const float* qrow = sm + i * QKVN + h * 32;
        float qv[32];
        #pragma unroll
        for (int k4 = 0; k4 < 8; k4++) {
            const float4 t = *(const float4*)&qrow[k4 * 4];
            qv[k4*4+0] = t.x; qv[k4*4+1] = t.y; qv[k4*4+2] = t.z; qv[k4*4+3] = t.w;
        }
        const float scale = 0.17677669529663687f;
        float lo[GSIZE];
        float mx = -1e30f;
        #pragma unroll 4
        for (int j = 0; j < GSIZE; j++) {
            const float* krow = sm + j * QKVN + HK + h * 32;
            float acc = 0.f;
            #pragma unroll
            for (int k4 = 0; k4 < 8; k4++) {
                const float4 t = *(const float4*)&krow[k4 * 4];
                acc += qv[k4*4+0] * t.x; acc += qv[k4*4+1] * t.y;
                acc += qv[k4*4+2] * t.z; acc += qv[k4*4+3] * t.w;
            }
            acc *= scale;
            lo[j] = acc;
            mx = fmaxf(mx, acc);
        }
        float s = 0.f;
        #pragma unroll
        for (int j = 0; j < GSIZE; j++) { lo[j] = __expf(lo[j] - mx); s += lo[j]; }
        const float inv = 1.f / s;

        float o[32];
        #pragma unroll
        for (int k = 0; k < 32; k++) o[k] = 0.f;
        #pragma unroll 4
        for (int j = 0; j < GSIZE; j++) {
            const float a = lo[j] * inv;
            const float* vrow = sm + j * QKVN + 2 * HK + h * 32;
            #pragma unroll
            for (int k4 = 0; k4 < 8; k4++) {
                const float4 t = *(const float4*)&vrow[k4 * 4];
                o[k4*4+0] += a * t.x; o[k4*4+1] += a * t.y;
                o[k4*4+2] += a * t.z; o[k4*4+3] += a * t.w;
            }
        }
        const size_t base = (size_t)(g * GSIZE + i) * HK + h * 32;
        #pragma unroll
        for (int c8 = 0; c8 < 4; c8++) {
            __align__(16) __nv_bfloat16 hb[8];
            __align__(16) __nv_bfloat16 lb[8];
            #pragma unroll
            for (int j = 0; j < 8; j++) split_bf16(o[c8 * 8 + j], hb[j], lb[j]);
            *(uint4*)&g_Ahi[base + c8 * 8] = *(uint4*)hb;
            *(uint4*)&g_Alo[base + c8 * 8] = *(uint4*)lb;
        }
    }
}

// ---------------------------------------------------------------------------
// Inputs: nodes, n_node, Wq, bq, Wk, bk, Wv, bv, Wo, bo.
// ---------------------------------------------------------------------------
extern "C" void kernel_launch(void* const* d_in, const int* in_sizes, int n_in,
                              void* d_out, int out_size)
{
    const float* nodes = (const float*)d_in[0];
    const float* Wq    = (const float*)d_in[2];
    const float* bq    = (const float*)d_in[3];
    const float* Wk    = (const float*)d_in[4];
    const float* bk    = (const float*)d_in[5];
    const float* Wv    = (const float*)d_in[6];
    const float* bv    = (const float*)d_in[7];
    const float* Wo    = (const float*)d_in[8];
    const float* bo    = (const float*)d_in[9];
    float* out = (float*)d_out;

    prep_all<<<536, 256>>>(nodes, Wq, bq, Wk, bk, Wv, bv, Wo);

    cudaFuncSetAttribute(qkv_gemm, cudaFuncAttributeMaxDynamicSharedMemorySize,
                         GEMM_SMEM);
    qkv_gemm<<<dim3(QKVN / BN, NODES / BM), 256, GEMM_SMEM>>>();

    attn2<<<GRAPHS, 256>>>();

    cudaFuncSetAttribute(out_gemm, cudaFuncAttributeMaxDynamicSharedMemorySize,
                         GEMM_SMEM);
    out_gemm<<<dim3(DOUT / BN, NODES / BM), 256, GEMM_SMEM>>>(bo, out);
}